// round 16
// baseline (speedup 1.0000x reference)
#include <cuda_runtime.h>
#include <cuda_fp16.h>
#include <cstdint>
#include <math.h>

#define NB  4
#define CIN 256
#define PL  128
#define HH  128
#define WW  128
#define HW  16384
#define KK  9
#define CK  1152   // PL*KK
#define LDP 136
#define LDA2 36    // k_dgemm A word stride (32 words + pad 4)
#define LDB2 136   // B word stride
#define LDV2 76    // Vs word stride
#define OLDB2 40   // offset-B word stride

// ---- scratch (device globals: allocation-free) ----
__device__ __half   g_nhwcH[NB*HW*PL];
__device__ float    g_ident[NB*PL*HW];
__device__ float    g_py[NB*KK*HW];
__device__ float    g_px[NB*KK*HW];
__device__ float    g_mk[NB*KK*HW];
__device__ uint32_t g_wOffH[(CK/2)*32];      // [kpair][o<27 pad 32] half2
__device__ uint32_t g_wDcH[(CK/2)*PL];       // [kpair][o] half2
__device__ uint32_t g_w3H[(PL/2)*PL];        // [cpair][o] half2
__device__ uint32_t g_w1H[(CIN/2)*PL];       // [cpair][o] half2
__device__ uint32_t g_wdsH[(CIN/2)*PL];      // [cpair][o] half2

// ---- mma helpers ----
__device__ __forceinline__ void mma_f16(float d[4], const uint32_t a[4], const uint32_t b[2]) {
    asm volatile("mma.sync.aligned.m16n8k16.row.col.f32.f16.f16.f32 "
        "{%0,%1,%2,%3}, {%4,%5,%6,%7}, {%8,%9}, {%0,%1,%2,%3};"
        : "+f"(d[0]), "+f"(d[1]), "+f"(d[2]), "+f"(d[3])
        : "r"(a[0]), "r"(a[1]), "r"(a[2]), "r"(a[3]), "r"(b[0]), "r"(b[1]));
}
__device__ __forceinline__ uint32_t f2h2(float lo, float hi) {
    __half2 h = __floats2half2_rn(lo, hi);
    return *(uint32_t*)&h;
}

// ---------------- K0: weight transposes + half2 packing ----------------
__global__ void k_prep(const float* __restrict__ w_off,
                       const float* __restrict__ w_dc,
                       const float* __restrict__ w3,
                       const float* __restrict__ w1,
                       const float* __restrict__ wds) {
    int i = blockIdx.x * blockDim.x + threadIdx.x;
    if (i < (CK/2)*32) {
        int kp = i >> 5, o = i & 31;
        int tap = kp >> 6, c0 = (kp & 63) * 2;
        uint32_t v = 0;
        if (o < 27)
            v = f2h2(w_off[o*CK + c0*KK + tap], w_off[o*CK + (c0 + 1)*KK + tap]);
        g_wOffH[i] = v;
    }
    if (i < (CK/2)*PL) {
        int kp = i >> 7, o = i & 127;
        int kk0 = 2*kp;
        int tap = kk0 >> 7, c0 = kk0 & 127;
        g_wDcH[i] = f2h2(w_dc[(o*PL + c0)*KK + tap], w_dc[(o*PL + c0 + 1)*KK + tap]);
    }
    if (i < (PL/2)*PL) {
        int kp = i >> 7, o = i & 127;
        g_w3H[i] = f2h2(w3[o*PL + 2*kp], w3[o*PL + 2*kp + 1]);
    }
    if (i < (CIN/2)*PL) {
        int kp = i >> 7, o = i & 127;
        g_w1H[i]  = f2h2(w1[o*CIN + 2*kp],  w1[o*CIN + 2*kp + 1]);
        g_wdsH[i] = f2h2(wds[o*CIN + 2*kp], wds[o*CIN + 2*kp + 1]);
    }
}

// ---- shared 1x1-conv GEMM core (K=256) ----
__device__ __forceinline__ void conv1x1_core(
    uint32_t* smw, const float* __restrict__ xb, const uint32_t* __restrict__ wH,
    int tid, int m0, int n0, int t3, int g, float acc[2][8][4])
{
    const int cp = tid >> 4;
    const int P1 = (tid & 15) * 4;
    const int P2 = 64 + P1;
    const int brr = tid >> 4;
    const int bc8 = (tid & 15) * 8;

    float4 sa0, sa1, sb0, sb1;
    uint4  sw0, sw1;
    auto ld = [&](int kc) {
        const float* ra = xb + (size_t)(kc*32 + 2*cp) * HW;
        sa0 = *(const float4*)(ra + P1);
        sa1 = *(const float4*)(ra + P2);
        sb0 = *(const float4*)(ra + HW + P1);
        sb1 = *(const float4*)(ra + HW + P2);
        const uint32_t* src = wH + ((size_t)kc*16 + brr)*PL + bc8;
        sw0 = *(const uint4*)src;
        sw1 = *(const uint4*)(src + 4);
    };
    auto sts = [&](int bf) {
        uint32_t* Aw = smw + bf * 2176;
        uint32_t* Bw = smw + 4352 + bf * 2176;
        uint4 w0 = make_uint4(f2h2(sa0.x, sb0.x), f2h2(sa0.y, sb0.y),
                              f2h2(sa0.z, sb0.z), f2h2(sa0.w, sb0.w));
        uint4 w1v = make_uint4(f2h2(sa1.x, sb1.x), f2h2(sa1.y, sb1.y),
                               f2h2(sa1.z, sb1.z), f2h2(sa1.w, sb1.w));
        *(uint4*)&Aw[cp*LDP + P1] = w0;
        *(uint4*)&Aw[cp*LDP + P2] = w1v;
        *(uint4*)&Bw[brr*LDB2 + bc8]     = sw0;
        *(uint4*)&Bw[brr*LDB2 + bc8 + 4] = sw1;
    };

    ld(0); sts(0);
    __syncthreads();

    for (int kc = 0; kc < 8; kc++) {
        if (kc < 7) ld(kc + 1);
        const uint32_t* As = smw + (kc & 1) * 2176;
        const uint32_t* Bs = smw + 4352 + (kc & 1) * 2176;
#pragma unroll
        for (int s = 0; s < 2; s++) {
            const int bs = s*8;
            uint32_t a[2][4];
#pragma unroll
            for (int mt = 0; mt < 2; mt++) {
                int rb = m0 + mt*16 + g;
                a[mt][0] = As[(bs + t3)*LDP + rb];
                a[mt][1] = As[(bs + t3)*LDP + rb + 8];
                a[mt][2] = As[(bs + t3 + 4)*LDP + rb];
                a[mt][3] = As[(bs + t3 + 4)*LDP + rb + 8];
            }
#pragma unroll
            for (int nt = 0; nt < 8; nt++) {
                uint32_t bb[2];
                bb[0] = Bs[(bs + t3)*LDB2 + n0 + nt*8 + g];
                bb[1] = Bs[(bs + t3 + 4)*LDB2 + n0 + nt*8 + g];
                mma_f16(acc[0][nt], a[0], bb);
                mma_f16(acc[1][nt], a[1], bb);
            }
        }
        if (kc < 7) sts((kc + 1) & 1);
        __syncthreads();
    }
}

// ---------------- K1: conv1 only (fp16 mma) ----------------
#define SMEM_TOT_C (17408 * 4)
__global__ __launch_bounds__(256, 2) void k_cgemm(
    const float* __restrict__ x,
    const float* __restrict__ s1a, const float* __restrict__ t1a,
    const float* __restrict__ s1b, const float* __restrict__ t1b)
{
    extern __shared__ __align__(16) float smf[];
    uint32_t* smw = (uint32_t*)smf;

    const int tid  = threadIdx.x;
    const int wrp  = tid >> 5;
    const int t3   = tid & 3;
    const int g    = (tid & 31) >> 2;
    const int m0   = (wrp & 3) * 32;
    const int n0   = (wrp >> 2) * 64;
    const int pos0 = blockIdx.x * 128;
    const int b    = blockIdx.y;
    const float* xb = x + (size_t)b * CIN * HW + pos0;

    float acc[2][8][4];
#pragma unroll
    for (int mt = 0; mt < 2; mt++)
#pragma unroll
        for (int nt = 0; nt < 8; nt++)
#pragma unroll
            for (int i = 0; i < 4; i++) acc[mt][nt][i] = 0.f;

    conv1x1_core(smw, xb, g_w1H, tid, m0, n0, t3, g, acc);

    float* Fs = smf;
#pragma unroll
    for (int nt = 0; nt < 8; nt++) {
        int c0 = n0 + nt*8 + 2*t3;
        float p0a = __ldg(s1a + c0),     p0b = __ldg(t1a + c0);
        float p0c = __ldg(s1b + c0),     p0d = __ldg(t1b + c0);
        float p1a = __ldg(s1a + c0 + 1), p1b = __ldg(t1a + c0 + 1);
        float p1c = __ldg(s1b + c0 + 1), p1d = __ldg(t1b + c0 + 1);
#pragma unroll
        for (int mt = 0; mt < 2; mt++) {
            int plo = m0 + mt*16 + g;
            float v0 = fmaxf(fmaxf(acc[mt][nt][0] * p0a + p0b, 0.f) * p0c + p0d, 0.f);
            float v1 = fmaxf(fmaxf(acc[mt][nt][1] * p1a + p1b, 0.f) * p1c + p1d, 0.f);
            float v2 = fmaxf(fmaxf(acc[mt][nt][2] * p0a + p0b, 0.f) * p0c + p0d, 0.f);
            float v3 = fmaxf(fmaxf(acc[mt][nt][3] * p1a + p1b, 0.f) * p1c + p1d, 0.f);
            Fs[c0*LDP + plo]           = v0;
            Fs[(c0 + 1)*LDP + plo]     = v1;
            Fs[c0*LDP + plo + 8]       = v2;
            Fs[(c0 + 1)*LDP + plo + 8] = v3;
        }
    }
    __syncthreads();

    const int o2 = tid & 127;
    const int ph = tid >> 7;
    size_t baseh = ((size_t)(b*HW + pos0 + o2))*PL + ph*64;
#pragma unroll
    for (int i = 0; i < 16; i++) {
        int c = ph*64 + i*4;
        uint32_t h0 = f2h2(Fs[c*LDP + o2],     Fs[(c+1)*LDP + o2]);
        uint32_t h1 = f2h2(Fs[(c+2)*LDP + o2], Fs[(c+3)*LDP + o2]);
        *(uint2*)&g_nhwcH[baseh + i*4] = make_uint2(h0, h1);
    }
}

// ---------------- K2: mixed kernel — even blocks: offset conv; odd blocks: downsample ----------------
__global__ __launch_bounds__(256, 2) void k_mix(
    const float* __restrict__ b_off,
    const float* __restrict__ x,
    const float* __restrict__ bds, const float* __restrict__ sd, const float* __restrict__ td)
{
    extern __shared__ __align__(16) float smf[];
    uint32_t* smw = (uint32_t*)smf;

    const int tid = threadIdx.x;
    const int blk = blockIdx.x;
    const int idx = blk >> 1;
    const int wrp = tid >> 5;
    const int t3  = tid & 3;
    const int g   = (tid & 31) >> 2;

    if ((blk & 1) == 0) {
        uint32_t* Aw = smw;
        uint32_t* Bw = smw + 4608;
        float*    So = (float*)(smw + 5888);

        const int lane = tid & 31;
        const int m0o  = wrp * 16;
        const int sp   = lane >> 3;
        const int cq   = lane & 7;
        const int h    = idx & 127;
        const int b    = idx >> 7;
        const __half* nh = g_nhwcH + (size_t)b * HW * PL;

        float acc[4][4];
#pragma unroll
        for (int nt = 0; nt < 4; nt++)
#pragma unroll
            for (int i = 0; i < 4; i++) acc[nt][i] = 0.f;

        for (int dc = 0; dc < 18; dc++) {
            const int tap = dc >> 1;
            const int c0  = (dc & 1) * 64;
            const int ky  = tap / 3;
            const int kx  = tap - 3*ky;
            const int yy  = h + ky - 1;
            const bool rv = ((unsigned)yy < HH);
#pragma unroll
            for (int it = 0; it < 4; it++) {
                int p  = wrp*16 + it*4 + sp;
                int xp = p + kx - 1;
                uint4 r = make_uint4(0u, 0u, 0u, 0u);
                if (rv && (unsigned)xp < WW)
                    r = *(const uint4*)(nh + ((size_t)yy*WW + xp)*PL + c0 + cq*8);
                *(uint4*)&Aw[p*LDA2 + cq*4] = r;
            }
            {
                int rr = tid >> 3, col4 = (tid & 7) * 4;
                *(uint4*)&Bw[rr*OLDB2 + col4] =
                    *(const uint4*)&g_wOffH[((size_t)dc*32 + rr)*32 + col4];
            }
            __syncthreads();
#pragma unroll
            for (int s = 0; s < 4; s++) {
                const int bs = s*8;
                uint32_t a[4];
                int rb = m0o + g;
                a[0] = Aw[rb*LDA2 + bs + t3];
                a[1] = Aw[(rb + 8)*LDA2 + bs + t3];
                a[2] = Aw[rb*LDA2 + bs + t3 + 4];
                a[3] = Aw[(rb + 8)*LDA2 + bs + t3 + 4];
#pragma unroll
                for (int nt = 0; nt < 4; nt++) {
                    uint32_t bb[2];
                    bb[0] = Bw[(bs + t3)*OLDB2 + nt*8 + g];
                    bb[1] = Bw[(bs + t3 + 4)*OLDB2 + nt*8 + g];
                    mma_f16(acc[nt], a, bb);
                }
            }
            __syncthreads();
        }

#pragma unroll
        for (int nt = 0; nt < 4; nt++) {
            int c0 = nt*8 + 2*t3;
            int plo = m0o + g;
            So[c0*LDP + plo]           = acc[nt][0];
            So[(c0 + 1)*LDP + plo]     = acc[nt][1];
            So[c0*LDP + plo + 8]       = acc[nt][2];
            So[(c0 + 1)*LDP + plo + 8] = acc[nt][3];
        }
        __syncthreads();

        const int p = tid & 127;
        const int half = tid >> 7;
        for (int k = half; k < 9; k += 2) {
            float dy = So[k*LDP + p]        + __ldg(b_off + k);
            float dx = So[(9 + k)*LDP + p]  + __ldg(b_off + 9 + k);
            float z  = So[(18 + k)*LDP + p] + __ldg(b_off + 18 + k);
            float mk = 1.f / (1.f + expf(-z));
            int oidx = (b*KK + k)*HW + h*WW + p;
            g_py[oidx] = (float)(h - 1 + k/3) + dy;
            g_px[oidx] = (float)(p - 1 + k%3) + dx;
            g_mk[oidx] = mk;
        }
    } else {
        const int m0   = (wrp & 3) * 32;
        const int n0   = (wrp >> 2) * 64;
        const int pos0 = (idx & 127) * 128;
        const int b    = idx >> 7;
        const float* xb = x + (size_t)b * CIN * HW + pos0;

        float acc[2][8][4];
#pragma unroll
        for (int mt = 0; mt < 2; mt++)
#pragma unroll
            for (int nt = 0; nt < 8; nt++)
#pragma unroll
                for (int i = 0; i < 4; i++) acc[mt][nt][i] = 0.f;

        conv1x1_core(smw, xb, g_wdsH, tid, m0, n0, t3, g, acc);

        float* Fs = smf;
#pragma unroll
        for (int nt = 0; nt < 8; nt++) {
            int c0 = n0 + nt*8 + 2*t3;
            float p0a = __ldg(bds + c0),     p0b = __ldg(sd + c0),     p0c = __ldg(td + c0);
            float p1a = __ldg(bds + c0 + 1), p1b = __ldg(sd + c0 + 1), p1c = __ldg(td + c0 + 1);
#pragma unroll
            for (int mt = 0; mt < 2; mt++) {
                int plo = m0 + mt*16 + g;
                Fs[c0*LDP + plo]           = (acc[mt][nt][0] + p0a) * p0b + p0c;
                Fs[(c0 + 1)*LDP + plo]     = (acc[mt][nt][1] + p1a) * p1b + p1c;
                Fs[c0*LDP + plo + 8]       = (acc[mt][nt][2] + p0a) * p0b + p0c;
                Fs[(c0 + 1)*LDP + plo + 8] = (acc[mt][nt][3] + p1a) * p1b + p1c;
            }
        }
        __syncthreads();

        const int o2 = tid & 127;
        const int ph = tid >> 7;
        size_t base = ((size_t)(b*PL + o2))*HW + pos0 + ph*64;
        const float* frow = Fs + o2*LDP + ph*64;
#pragma unroll
        for (int i = 0; i < 16; i++)
            *(float4*)&g_ident[base + i*4] = *(const float4*)&frow[i*4];
    }
}

// ---------------- K3: deform GEMM, fp16 mma, double-buffered interleaved pipeline ----------------
// words: A[2][128*36] @0 (9216), B[2][32*136] @9216 (8704), cE @17920 (9216) -> 27136 words
// tail:  Vs [128][76] @0 (9728), B2 [32*136] @9728 (4352); Fs f32 [128][136] (17408) all fit.
#define SMF_A   0
#define SMF_B   9216
#define SMF_CE  17920
#define SMF_V   0
#define SMF_B2  9728
#define SMEM_TOT (27136 * 4)

__global__ __launch_bounds__(256, 2) void k_dgemm(
    const float* __restrict__ b_dc, const float* __restrict__ s2, const float* __restrict__ t2,
    const float* __restrict__ s3a, const float* __restrict__ t3a,
    const float* __restrict__ s3b, const float* __restrict__ t3b,
    float* __restrict__ out)
{
    extern __shared__ __align__(16) float smf[];
    uint32_t* smw = (uint32_t*)smf;
    float* cE = smf + SMF_CE;

    const int tid  = threadIdx.x;
    const int wrp  = tid >> 5;
    const int lane = tid & 31;
    const int t3   = tid & 3;
    const int g    = (tid & 31) >> 2;
    const int m0   = (wrp & 3) * 32;
    const int n0   = (wrp >> 2) * 64;
    const int sp   = lane >> 3;
    const int cq   = lane & 7;
    const int pos0 = blockIdx.x * 128;
    const int b    = pos0 >> 14;
    const int pim0 = pos0 & (HW - 1);

    for (int idx = tid; idx < 1152; idx += 256) {
        int k = idx >> 7, p = idx & 127;
        int gidx = (b*KK + k)*HW + pim0 + p;
        float py = g_py[gidx], px = g_px[gidx], mk = g_mk[gidx];
        float fy = floorf(py), fx = floorf(px);
        float wy = py - fy, wx = px - fx;
        int y0 = (int)fy, x0 = (int)fx;
        bool y0k = ((unsigned)y0 < HH), y1k = ((unsigned)(y0+1) < HH);
        bool x0k = ((unsigned)x0 < WW), x1k = ((unsigned)(x0+1) < WW);
        float w00 = (y0k && x0k) ? (1.f-wy)*(1.f-wx)*mk : 0.f;
        float w01 = (y0k && x1k) ? (1.f-wy)*wx*mk       : 0.f;
        float w10 = (y1k && x0k) ? wy*(1.f-wx)*mk       : 0.f;
        float w11 = (y1k && x1k) ? wy*wx*mk             : 0.f;
        int iy0 = min(max(y0, 0), HH-1),     ix0 = min(max(x0, 0), WW-1);
        int iy1 = min(max(y0 + 1, 0), HH-1), ix1 = min(max(x0 + 1, 0), WW-1);
        float* e = cE + idx*8;
        ((uint32_t*)e)[0] = f2h2(w00, w00);
        ((uint32_t*)e)[1] = f2h2(w01, w01);
        ((uint32_t*)e)[2] = f2h2(w10, w10);
        ((uint32_t*)e)[3] = f2h2(w11, w11);
        ((int*)e)[4] = (iy0*WW + ix0)*PL;
        ((int*)e)[5] = (iy0*WW + ix1)*PL;
        ((int*)e)[6] = (iy1*WW + ix0)*PL;
        ((int*)e)[7] = (iy1*WW + ix1)*PL;
    }
    __syncthreads();

    const __half* nhwcH = g_nhwcH + (size_t)b * HW * PL;

    float acc[2][8][4];
#pragma unroll
    for (int mt = 0; mt < 2; mt++)
#pragma unroll
        for (int nt = 0; nt < 8; nt++)
#pragma unroll
            for (int i = 0; i < 4; i++) acc[mt][nt][i] = 0.f;

    // prologue: full fill of chunk 0 into buffer 0
    {
        uint32_t* Aw = smw + SMF_A;
        uint32_t* Bw = smw + SMF_B;
#pragma unroll
        for (int it = 0; it < 4; it++) {
            int p  = wrp*16 + it*4 + sp;
            const uint4 wb = *(const uint4*)(cE + p*8);
            const int4  iv = *(const int4*)(cE + p*8 + 4);
            __half2 H0 = *(__half2*)&wb.x;
            __half2 H1 = *(__half2*)&wb.y;
            __half2 H2 = *(__half2*)&wb.z;
            __half2 H3 = *(__half2*)&wb.w;
            const __half* base = nhwcH + cq*8;
            uint4 r0 = *(const uint4*)(base + iv.x);
            uint4 r1 = *(const uint4*)(base + iv.y);
            uint4 r2 = *(const uint4*)(base + iv.z);
            uint4 r3 = *(const uint4*)(base + iv.w);
            uint32_t o4[4];
#pragma unroll
            for (int j = 0; j < 4; j++) {
                __half2 s = __hmul2(((__half2*)&r0)[j], H0);
                s = __hfma2(((__half2*)&r1)[j], H1, s);
                s = __hfma2(((__half2*)&r2)[j], H2, s);
                s = __hfma2(((__half2*)&r3)[j], H3, s);
                o4[j] = *(uint32_t*)&s;
            }
            *(uint4*)&Aw[p*LDA2 + cq*4] = make_uint4(o4[0], o4[1], o4[2], o4[3]);
            int q = it*256 + tid, rr = q >> 5, col4 = (q & 31) * 4;
            *(uint4*)&Bw[rr*LDB2 + col4] = *(const uint4*)&g_wDcH[(size_t)rr*PL + col4];
        }
    }
    __syncthreads();

    for (int dc = 0; dc < 18; dc++) {
        const int cur = dc & 1;
        const int nxt = cur ^ 1;
        const int dn  = dc + 1;
        const bool more = (dn < 18);
        const uint32_t* As = smw + SMF_A + cur*4608;
        const uint32_t* Bs = smw + SMF_B + cur*4352;
        uint32_t* An = smw + SMF_A + nxt*4608;
        uint32_t* Bn = smw + SMF_B + nxt*4352;
#pragma unroll
        for (int it = 0; it < 4; it++) {
            // issue next-chunk loads for subfill `it`
            uint4 r0, r1, r2, r3, wb, bwv;
            int4 iv;
            int pA = 0, pB = 0;
            if (more) {
                int p  = wrp*16 + it*4 + sp;
                int ci = (dn >> 1)*128 + p;
                wb = *(const uint4*)(cE + ci*8);
                iv = *(const int4*)(cE + ci*8 + 4);
                const __half* base = nhwcH + ((dn & 1) * 64) + cq*8;
                r0 = *(const uint4*)(base + iv.x);
                r1 = *(const uint4*)(base + iv.y);
                r2 = *(const uint4*)(base + iv.z);
                r3 = *(const uint4*)(base + iv.w);
                pA = p*LDA2 + cq*4;
                int q = it*256 + tid, rr = q >> 5, col4 = (q & 31) * 4;
                bwv = *(const uint4*)&g_wDcH[((size_t)dn*32 + rr)*PL + col4];
                pB = rr*LDB2 + col4;
            }
            // mma sub-block `it` of current chunk (covers LDG latency)
            const int bs = it*8;
            uint32_t a[2][4];
#pragma unroll
            for (int mt = 0; mt < 2; mt++) {
                int rb = m0 + mt*16 + g;
                a[mt][0] = As[rb*LDA2 + bs + t3];
                a[mt][1] = As[(rb + 8)*LDA2 + bs + t3];
                a[mt][2] = As[rb*LDA2 + bs + t3 + 4];
                a[mt][3] = As[(rb + 8)*LDA2 + bs + t3 + 4];
            }
#pragma unroll
            for (int nt = 0; nt < 8; nt++) {
                uint32_t bb[2];
                bb[0] = Bs[(bs + t3)*LDB2 + n0 + nt*8 + g];
                bb[1] = Bs[(bs + t3 + 4)*LDB2 + n0 + nt*8 + g];
                mma_f16(acc[0][nt], a[0], bb);
                mma_f16(acc[1][nt], a[1], bb);
            }
            // blend + store next-chunk tiles
            if (more) {
                __half2 H0 = *(__half2*)&wb.x;
                __half2 H1 = *(__half2*)&wb.y;
                __half2 H2 = *(__half2*)&wb.z;
                __half2 H3 = *(__half2*)&wb.w;
                uint32_t o4[4];
#pragma unroll
                for (int j = 0; j < 4; j++) {
                    __half2 s = __hmul2(((__half2*)&r0)[j], H0);
                    s = __hfma2(((__half2*)&r1)[j], H1, s);
                    s = __hfma2(((__half2*)&r2)[j], H2, s);
                    s = __hfma2(((__half2*)&r3)[j], H3, s);
                    o4[j] = *(uint32_t*)&s;
                }
                *(uint4*)&An[pA] = make_uint4(o4[0], o4[1], o4[2], o4[3]);
                *(uint4*)&Bn[pB] = bwv;
            }
        }
        __syncthreads();
    }

    uint32_t* Vw = smw + SMF_V;
#pragma unroll
    for (int nt = 0; nt < 8; nt++) {
        int c0 = n0 + nt*8 + 2*t3;
        float b0 = __ldg(b_dc + c0),     ss0 = __ldg(s2 + c0),     tt0 = __ldg(t2 + c0);
        float b1 = __ldg(b_dc + c0 + 1), ss1 = __ldg(s2 + c0 + 1), tt1 = __ldg(t2 + c0 + 1);
#pragma unroll
        for (int mt = 0; mt < 2; mt++) {
            int plo = m0 + mt*16 + g;
            float v0 = fmaxf((acc[mt][nt][0] + b0) * ss0 + tt0, 0.f);
            float v1 = fmaxf((acc[mt][nt][1] + b1) * ss1 + tt1, 0.f);
            float v2 = fmaxf((acc[mt][nt][2] + b0) * ss0 + tt0, 0.f);
            float v3 = fmaxf((acc[mt][nt][3] + b1) * ss1 + tt1, 0.f);
            Vw[plo*LDV2 + (c0 >> 1)]       = f2h2(v0, v1);
            Vw[(plo + 8)*LDV2 + (c0 >> 1)] = f2h2(v2, v3);
        }
    }
    __syncthreads();

    float acc3[2][8][4];
#pragma unroll
    for (int mt = 0; mt < 2; mt++)
#pragma unroll
        for (int nt = 0; nt < 8; nt++)
#pragma unroll
            for (int i = 0; i < 4; i++) acc3[mt][nt][i] = 0.f;

    uint32_t* B2w = smw + SMF_B2;
    for (int d2 = 0; d2 < 2; d2++) {
#pragma unroll
        for (int u = 0; u < 4; u++) {
            int q = u*256 + tid, rr = q >> 5, col4 = (q & 31) * 4;
            *(uint4*)&B2w[rr*LDB2 + col4] =
                *(const uint4*)&g_w3H[((size_t)d2*32 + rr)*PL + col4];
        }
        __syncthreads();
#pragma unroll
        for (int s = 0; s < 4; s++) {
            const int bs = s*8;
            const int kw = d2*32 + bs;
            uint32_t a[2][4];
#pragma unroll
            for (int mt = 0; mt < 2; mt++) {
                int rb = m0 + mt*16 + g;
                a[mt][0] = Vw[rb*LDV2 + kw + t3];
                a[mt][1] = Vw[(rb + 8)*LDV2 + kw + t3];
                a[mt][2] = Vw[rb*LDV2 + kw + t3 + 4];
                a[mt][3] = Vw[(rb + 8)*LDV2 + kw + t3 + 4];
            }
#pragma unroll
            for (int nt = 0; nt < 8; nt++) {
                uint32_t bb[2];
                bb[0] = B2w[(bs + t3)*LDB2 + n0 + nt*8 + g];
                bb[1] = B2w[(bs + t3 + 4)*LDB2 + n0 + nt*8 + g];
                mma_f16(acc3[0][nt], a[0], bb);
                mma_f16(acc3[1][nt], a[1], bb);
            }
        }
        __syncthreads();
    }

    float* Fs = smf + SMF_V;
#pragma unroll
    for (int nt = 0; nt < 8; nt++) {
        int c0 = n0 + nt*8 + 2*t3;
        float sa0 = __ldg(s3a + c0),     ta0 = __ldg(t3a + c0);
        float sb0 = __ldg(s3b + c0),     tb0 = __ldg(t3b + c0);
        float sa1 = __ldg(s3a + c0 + 1), ta1 = __ldg(t3a + c0 + 1);
        float sb1 = __ldg(s3b + c0 + 1), tb1 = __ldg(t3b + c0 + 1);
#pragma unroll
        for (int mt = 0; mt < 2; mt++) {
            int plo = m0 + mt*16 + g;
            Fs[c0*LDP + plo]           = fmaxf(acc3[mt][nt][0] * sa0 + ta0, 0.f) * sb0 + tb0;
            Fs[(c0 + 1)*LDP + plo]     = fmaxf(acc3[mt][nt][1] * sa1 + ta1, 0.f) * sb1 + tb1;
            Fs[c0*LDP + plo + 8]       = fmaxf(acc3[mt][nt][2] * sa0 + ta0, 0.f) * sb0 + tb0;
            Fs[(c0 + 1)*LDP + plo + 8] = fmaxf(acc3[mt][nt][3] * sa1 + ta1, 0.f) * sb1 + tb1;
        }
    }
    __syncthreads();

    {
        const int o2 = tid & 127;
        const int ph = tid >> 7;
        size_t base = ((size_t)(b*PL + o2))*HW + pim0 + ph*64;
        const float* frow = Fs + o2*LDP + ph*64;
#pragma unroll
        for (int i = 0; i < 16; i++) {
            float4 f = *(const float4*)&frow[i*4];
            float4 id = *(const float4*)&g_ident[base + i*4];
            *(float4*)&out[base + i*4] = make_float4(
                fmaxf(f.x + id.x, 0.f), fmaxf(f.y + id.y, 0.f),
                fmaxf(f.z + id.z, 0.f), fmaxf(f.w + id.w, 0.f));
        }
    }
}

// ---------------- host ----------------
extern "C" void kernel_launch(void* const* d_in, const int* in_sizes, int n_in,
                              void* d_out, int out_size) {
    const float* x    = (const float*)d_in[0];
    const float* w1   = (const float*)d_in[1];
    const float* s1a  = (const float*)d_in[2];
    const float* t1a  = (const float*)d_in[3];
    const float* s1b  = (const float*)d_in[4];
    const float* t1b  = (const float*)d_in[5];
    const float* w_off= (const float*)d_in[6];
    const float* b_off= (const float*)d_in[7];
    const float* w_dc = (const float*)d_in[8];
    const float* b_dc = (const float*)d_in[9];
    const float* s2   = (const float*)d_in[10];
    const float* t2   = (const float*)d_in[11];
    const float* w3   = (const float*)d_in[12];
    const float* s3a  = (const float*)d_in[13];
    const float* t3a  = (const float*)d_in[14];
    const float* s3b  = (const float*)d_in[15];
    const float* t3b  = (const float*)d_in[16];
    const float* w_ds = (const float*)d_in[17];
    const float* b_ds = (const float*)d_in[18];
    const float* sd   = (const float*)d_in[19];
    const float* td   = (const float*)d_in[20];
    float* out = (float*)d_out;

    k_prep<<<(CK*PL/2 + 255)/256, 256>>>(w_off, w_dc, w3, w1, w_ds);

    cudaFuncSetAttribute(k_cgemm, cudaFuncAttributeMaxDynamicSharedMemorySize, SMEM_TOT_C);
    dim3 g1(HW/128, NB);
    k_cgemm<<<g1, 256, SMEM_TOT_C>>>(x, s1a, t1a, s1b, t1b);

    cudaFuncSetAttribute(k_mix, cudaFuncAttributeMaxDynamicSharedMemorySize, SMEM_TOT_C);
    k_mix<<<2*NB*HH, 256, SMEM_TOT_C>>>(b_off, x, b_ds, sd, td);

    cudaFuncSetAttribute(k_dgemm, cudaFuncAttributeMaxDynamicSharedMemorySize, SMEM_TOT);
    k_dgemm<<<NB*HW/128, 256, SMEM_TOT>>>(b_dc, s2, t2, s3a, t3a, s3b, t3b, out);
}

// round 17
// speedup vs baseline: 1.0227x; 1.0227x over previous
#include <cuda_runtime.h>
#include <cuda_fp16.h>
#include <cstdint>
#include <math.h>

#define NB  4
#define CIN 256
#define PL  128
#define HH  128
#define WW  128
#define HW  16384
#define KK  9
#define CK  1152   // PL*KK
#define LDP 136
#define LDA2 36    // k_mix offset-A word stride
#define LDA3 68    // k_dgemm A word stride (64 words + pad 4)
#define LDB2 136   // B word stride
#define LDV2 76    // Vs word stride
#define OLDB2 40   // offset-B word stride

// ---- scratch (device globals: allocation-free) ----
__device__ __half   g_nhwcH[NB*HW*PL];
__device__ float    g_ident[NB*PL*HW];
__device__ float    g_py[NB*KK*HW];
__device__ float    g_px[NB*KK*HW];
__device__ float    g_mk[NB*KK*HW];
__device__ uint32_t g_wOffH[(CK/2)*32];      // [kpair][o<27 pad 32] half2
__device__ uint32_t g_wDcH[(CK/2)*PL];       // [kpair][o] half2
__device__ uint32_t g_w3H[(PL/2)*PL];        // [cpair][o] half2
__device__ uint32_t g_w1H[(CIN/2)*PL];       // [cpair][o] half2
__device__ uint32_t g_wdsH[(CIN/2)*PL];      // [cpair][o] half2

// ---- mma helpers ----
__device__ __forceinline__ void mma_f16(float d[4], const uint32_t a[4], const uint32_t b[2]) {
    asm volatile("mma.sync.aligned.m16n8k16.row.col.f32.f16.f16.f32 "
        "{%0,%1,%2,%3}, {%4,%5,%6,%7}, {%8,%9}, {%0,%1,%2,%3};"
        : "+f"(d[0]), "+f"(d[1]), "+f"(d[2]), "+f"(d[3])
        : "r"(a[0]), "r"(a[1]), "r"(a[2]), "r"(a[3]), "r"(b[0]), "r"(b[1]));
}
__device__ __forceinline__ uint32_t f2h2(float lo, float hi) {
    __half2 h = __floats2half2_rn(lo, hi);
    return *(uint32_t*)&h;
}

// ---------------- K0: weight transposes + half2 packing ----------------
__global__ void k_prep(const float* __restrict__ w_off,
                       const float* __restrict__ w_dc,
                       const float* __restrict__ w3,
                       const float* __restrict__ w1,
                       const float* __restrict__ wds) {
    int i = blockIdx.x * blockDim.x + threadIdx.x;
    if (i < (CK/2)*32) {
        int kp = i >> 5, o = i & 31;
        int tap = kp >> 6, c0 = (kp & 63) * 2;
        uint32_t v = 0;
        if (o < 27)
            v = f2h2(w_off[o*CK + c0*KK + tap], w_off[o*CK + (c0 + 1)*KK + tap]);
        g_wOffH[i] = v;
    }
    if (i < (CK/2)*PL) {
        int kp = i >> 7, o = i & 127;
        int kk0 = 2*kp;
        int tap = kk0 >> 7, c0 = kk0 & 127;
        g_wDcH[i] = f2h2(w_dc[(o*PL + c0)*KK + tap], w_dc[(o*PL + c0 + 1)*KK + tap]);
    }
    if (i < (PL/2)*PL) {
        int kp = i >> 7, o = i & 127;
        g_w3H[i] = f2h2(w3[o*PL + 2*kp], w3[o*PL + 2*kp + 1]);
    }
    if (i < (CIN/2)*PL) {
        int kp = i >> 7, o = i & 127;
        g_w1H[i]  = f2h2(w1[o*CIN + 2*kp],  w1[o*CIN + 2*kp + 1]);
        g_wdsH[i] = f2h2(wds[o*CIN + 2*kp], wds[o*CIN + 2*kp + 1]);
    }
}

// ---- shared 1x1-conv GEMM core (K=256) ----
__device__ __forceinline__ void conv1x1_core(
    uint32_t* smw, const float* __restrict__ xb, const uint32_t* __restrict__ wH,
    int tid, int m0, int n0, int t3, int g, float acc[2][8][4])
{
    const int cp = tid >> 4;
    const int P1 = (tid & 15) * 4;
    const int P2 = 64 + P1;
    const int brr = tid >> 4;
    const int bc8 = (tid & 15) * 8;

    float4 sa0, sa1, sb0, sb1;
    uint4  sw0, sw1;
    auto ld = [&](int kc) {
        const float* ra = xb + (size_t)(kc*32 + 2*cp) * HW;
        sa0 = *(const float4*)(ra + P1);
        sa1 = *(const float4*)(ra + P2);
        sb0 = *(const float4*)(ra + HW + P1);
        sb1 = *(const float4*)(ra + HW + P2);
        const uint32_t* src = wH + ((size_t)kc*16 + brr)*PL + bc8;
        sw0 = *(const uint4*)src;
        sw1 = *(const uint4*)(src + 4);
    };
    auto sts = [&](int bf) {
        uint32_t* Aw = smw + bf * 2176;
        uint32_t* Bw = smw + 4352 + bf * 2176;
        uint4 w0 = make_uint4(f2h2(sa0.x, sb0.x), f2h2(sa0.y, sb0.y),
                              f2h2(sa0.z, sb0.z), f2h2(sa0.w, sb0.w));
        uint4 w1v = make_uint4(f2h2(sa1.x, sb1.x), f2h2(sa1.y, sb1.y),
                               f2h2(sa1.z, sb1.z), f2h2(sa1.w, sb1.w));
        *(uint4*)&Aw[cp*LDP + P1] = w0;
        *(uint4*)&Aw[cp*LDP + P2] = w1v;
        *(uint4*)&Bw[brr*LDB2 + bc8]     = sw0;
        *(uint4*)&Bw[brr*LDB2 + bc8 + 4] = sw1;
    };

    ld(0); sts(0);
    __syncthreads();

    for (int kc = 0; kc < 8; kc++) {
        if (kc < 7) ld(kc + 1);
        const uint32_t* As = smw + (kc & 1) * 2176;
        const uint32_t* Bs = smw + 4352 + (kc & 1) * 2176;
#pragma unroll
        for (int s = 0; s < 2; s++) {
            const int bs = s*8;
            uint32_t a[2][4];
#pragma unroll
            for (int mt = 0; mt < 2; mt++) {
                int rb = m0 + mt*16 + g;
                a[mt][0] = As[(bs + t3)*LDP + rb];
                a[mt][1] = As[(bs + t3)*LDP + rb + 8];
                a[mt][2] = As[(bs + t3 + 4)*LDP + rb];
                a[mt][3] = As[(bs + t3 + 4)*LDP + rb + 8];
            }
#pragma unroll
            for (int nt = 0; nt < 8; nt++) {
                uint32_t bb[2];
                bb[0] = Bs[(bs + t3)*LDB2 + n0 + nt*8 + g];
                bb[1] = Bs[(bs + t3 + 4)*LDB2 + n0 + nt*8 + g];
                mma_f16(acc[0][nt], a[0], bb);
                mma_f16(acc[1][nt], a[1], bb);
            }
        }
        if (kc < 7) sts((kc + 1) & 1);
        __syncthreads();
    }
}

// ---------------- K1: conv1 only (fp16 mma) ----------------
#define SMEM_TOT_C (17408 * 4)
__global__ __launch_bounds__(256, 2) void k_cgemm(
    const float* __restrict__ x,
    const float* __restrict__ s1a, const float* __restrict__ t1a,
    const float* __restrict__ s1b, const float* __restrict__ t1b)
{
    extern __shared__ __align__(16) float smf[];
    uint32_t* smw = (uint32_t*)smf;

    const int tid  = threadIdx.x;
    const int wrp  = tid >> 5;
    const int t3   = tid & 3;
    const int g    = (tid & 31) >> 2;
    const int m0   = (wrp & 3) * 32;
    const int n0   = (wrp >> 2) * 64;
    const int pos0 = blockIdx.x * 128;
    const int b    = blockIdx.y;
    const float* xb = x + (size_t)b * CIN * HW + pos0;

    float acc[2][8][4];
#pragma unroll
    for (int mt = 0; mt < 2; mt++)
#pragma unroll
        for (int nt = 0; nt < 8; nt++)
#pragma unroll
            for (int i = 0; i < 4; i++) acc[mt][nt][i] = 0.f;

    conv1x1_core(smw, xb, g_w1H, tid, m0, n0, t3, g, acc);

    float* Fs = smf;
#pragma unroll
    for (int nt = 0; nt < 8; nt++) {
        int c0 = n0 + nt*8 + 2*t3;
        float p0a = __ldg(s1a + c0),     p0b = __ldg(t1a + c0);
        float p0c = __ldg(s1b + c0),     p0d = __ldg(t1b + c0);
        float p1a = __ldg(s1a + c0 + 1), p1b = __ldg(t1a + c0 + 1);
        float p1c = __ldg(s1b + c0 + 1), p1d = __ldg(t1b + c0 + 1);
#pragma unroll
        for (int mt = 0; mt < 2; mt++) {
            int plo = m0 + mt*16 + g;
            float v0 = fmaxf(fmaxf(acc[mt][nt][0] * p0a + p0b, 0.f) * p0c + p0d, 0.f);
            float v1 = fmaxf(fmaxf(acc[mt][nt][1] * p1a + p1b, 0.f) * p1c + p1d, 0.f);
            float v2 = fmaxf(fmaxf(acc[mt][nt][2] * p0a + p0b, 0.f) * p0c + p0d, 0.f);
            float v3 = fmaxf(fmaxf(acc[mt][nt][3] * p1a + p1b, 0.f) * p1c + p1d, 0.f);
            Fs[c0*LDP + plo]           = v0;
            Fs[(c0 + 1)*LDP + plo]     = v1;
            Fs[c0*LDP + plo + 8]       = v2;
            Fs[(c0 + 1)*LDP + plo + 8] = v3;
        }
    }
    __syncthreads();

    const int o2 = tid & 127;
    const int ph = tid >> 7;
    size_t baseh = ((size_t)(b*HW + pos0 + o2))*PL + ph*64;
#pragma unroll
    for (int i = 0; i < 16; i++) {
        int c = ph*64 + i*4;
        uint32_t h0 = f2h2(Fs[c*LDP + o2],     Fs[(c+1)*LDP + o2]);
        uint32_t h1 = f2h2(Fs[(c+2)*LDP + o2], Fs[(c+3)*LDP + o2]);
        *(uint2*)&g_nhwcH[baseh + i*4] = make_uint2(h0, h1);
    }
}

// ---------------- K2: mixed kernel — even blocks: offset conv; odd blocks: downsample ----------------
__global__ __launch_bounds__(256, 2) void k_mix(
    const float* __restrict__ b_off,
    const float* __restrict__ x,
    const float* __restrict__ bds, const float* __restrict__ sd, const float* __restrict__ td)
{
    extern __shared__ __align__(16) float smf[];
    uint32_t* smw = (uint32_t*)smf;

    const int tid = threadIdx.x;
    const int blk = blockIdx.x;
    const int idx = blk >> 1;
    const int wrp = tid >> 5;
    const int t3  = tid & 3;
    const int g   = (tid & 31) >> 2;

    if ((blk & 1) == 0) {
        uint32_t* Aw = smw;
        uint32_t* Bw = smw + 4608;
        float*    So = (float*)(smw + 5888);

        const int lane = tid & 31;
        const int m0o  = wrp * 16;
        const int sp   = lane >> 3;
        const int cq   = lane & 7;
        const int h    = idx & 127;
        const int b    = idx >> 7;
        const __half* nh = g_nhwcH + (size_t)b * HW * PL;

        float acc[4][4];
#pragma unroll
        for (int nt = 0; nt < 4; nt++)
#pragma unroll
            for (int i = 0; i < 4; i++) acc[nt][i] = 0.f;

        for (int dc = 0; dc < 18; dc++) {
            const int tap = dc >> 1;
            const int c0  = (dc & 1) * 64;
            const int ky  = tap / 3;
            const int kx  = tap - 3*ky;
            const int yy  = h + ky - 1;
            const bool rv = ((unsigned)yy < HH);
#pragma unroll
            for (int it = 0; it < 4; it++) {
                int p  = wrp*16 + it*4 + sp;
                int xp = p + kx - 1;
                uint4 r = make_uint4(0u, 0u, 0u, 0u);
                if (rv && (unsigned)xp < WW)
                    r = *(const uint4*)(nh + ((size_t)yy*WW + xp)*PL + c0 + cq*8);
                *(uint4*)&Aw[p*LDA2 + cq*4] = r;
            }
            {
                int rr = tid >> 3, col4 = (tid & 7) * 4;
                *(uint4*)&Bw[rr*OLDB2 + col4] =
                    *(const uint4*)&g_wOffH[((size_t)dc*32 + rr)*32 + col4];
            }
            __syncthreads();
#pragma unroll
            for (int s = 0; s < 4; s++) {
                const int bs = s*8;
                uint32_t a[4];
                int rb = m0o + g;
                a[0] = Aw[rb*LDA2 + bs + t3];
                a[1] = Aw[(rb + 8)*LDA2 + bs + t3];
                a[2] = Aw[rb*LDA2 + bs + t3 + 4];
                a[3] = Aw[(rb + 8)*LDA2 + bs + t3 + 4];
#pragma unroll
                for (int nt = 0; nt < 4; nt++) {
                    uint32_t bb[2];
                    bb[0] = Bw[(bs + t3)*OLDB2 + nt*8 + g];
                    bb[1] = Bw[(bs + t3 + 4)*OLDB2 + nt*8 + g];
                    mma_f16(acc[nt], a, bb);
                }
            }
            __syncthreads();
        }

#pragma unroll
        for (int nt = 0; nt < 4; nt++) {
            int c0 = nt*8 + 2*t3;
            int plo = m0o + g;
            So[c0*LDP + plo]           = acc[nt][0];
            So[(c0 + 1)*LDP + plo]     = acc[nt][1];
            So[c0*LDP + plo + 8]       = acc[nt][2];
            So[(c0 + 1)*LDP + plo + 8] = acc[nt][3];
        }
        __syncthreads();

        const int p = tid & 127;
        const int half = tid >> 7;
        for (int k = half; k < 9; k += 2) {
            float dy = So[k*LDP + p]        + __ldg(b_off + k);
            float dx = So[(9 + k)*LDP + p]  + __ldg(b_off + 9 + k);
            float z  = So[(18 + k)*LDP + p] + __ldg(b_off + 18 + k);
            float mk = 1.f / (1.f + expf(-z));
            int oidx = (b*KK + k)*HW + h*WW + p;
            g_py[oidx] = (float)(h - 1 + k/3) + dy;
            g_px[oidx] = (float)(p - 1 + k%3) + dx;
            g_mk[oidx] = mk;
        }
    } else {
        const int m0   = (wrp & 3) * 32;
        const int n0   = (wrp >> 2) * 64;
        const int pos0 = (idx & 127) * 128;
        const int b    = idx >> 7;
        const float* xb = x + (size_t)b * CIN * HW + pos0;

        float acc[2][8][4];
#pragma unroll
        for (int mt = 0; mt < 2; mt++)
#pragma unroll
            for (int nt = 0; nt < 8; nt++)
#pragma unroll
                for (int i = 0; i < 4; i++) acc[mt][nt][i] = 0.f;

        conv1x1_core(smw, xb, g_wdsH, tid, m0, n0, t3, g, acc);

        float* Fs = smf;
#pragma unroll
        for (int nt = 0; nt < 8; nt++) {
            int c0 = n0 + nt*8 + 2*t3;
            float p0a = __ldg(bds + c0),     p0b = __ldg(sd + c0),     p0c = __ldg(td + c0);
            float p1a = __ldg(bds + c0 + 1), p1b = __ldg(sd + c0 + 1), p1c = __ldg(td + c0 + 1);
#pragma unroll
            for (int mt = 0; mt < 2; mt++) {
                int plo = m0 + mt*16 + g;
                Fs[c0*LDP + plo]           = (acc[mt][nt][0] + p0a) * p0b + p0c;
                Fs[(c0 + 1)*LDP + plo]     = (acc[mt][nt][1] + p1a) * p1b + p1c;
                Fs[c0*LDP + plo + 8]       = (acc[mt][nt][2] + p0a) * p0b + p0c;
                Fs[(c0 + 1)*LDP + plo + 8] = (acc[mt][nt][3] + p1a) * p1b + p1c;
            }
        }
        __syncthreads();

        const int o2 = tid & 127;
        const int ph = tid >> 7;
        size_t base = ((size_t)(b*PL + o2))*HW + pos0 + ph*64;
        const float* frow = Fs + o2*LDP + ph*64;
#pragma unroll
        for (int i = 0; i < 16; i++)
            *(float4*)&g_ident[base + i*4] = *(const float4*)&frow[i*4];
    }
}

// ---------------- K3: deform GEMM, fp16 mma, full-tap chunks (9 chunks, 18 barriers) ----------------
// words: A [128][68] @0 (8704), B [64][136] @8704 (8704), cE @17408 (9216) -> 26624 words
// tail:  Vs [128][76] @0 (9728), B2 @9728 (4352); Fs f32 [128][136] (17408) all fit.
#define SMF_A   0
#define SMF_B   8704
#define SMF_CE  17408
#define SMF_V   0
#define SMF_B2  9728
#define SMEM_TOT (26624 * 4)

__global__ __launch_bounds__(256, 2) void k_dgemm(
    const float* __restrict__ b_dc, const float* __restrict__ s2, const float* __restrict__ t2,
    const float* __restrict__ s3a, const float* __restrict__ t3a,
    const float* __restrict__ s3b, const float* __restrict__ t3b,
    float* __restrict__ out)
{
    extern __shared__ __align__(16) float smf[];
    uint32_t* smw = (uint32_t*)smf;
    float* cE = smf + SMF_CE;

    const int tid  = threadIdx.x;
    const int wrp  = tid >> 5;
    const int lane = tid & 31;
    const int t3   = tid & 3;
    const int g    = (tid & 31) >> 2;
    const int m0   = (wrp & 3) * 32;
    const int n0   = (wrp >> 2) * 64;
    const int sp2  = lane >> 4;      // subpos 0..1
    const int cq2  = lane & 15;      // channel octet 0..15 (8 halfs each, covers 128)
    const int pos0 = blockIdx.x * 128;
    const int b    = pos0 >> 14;
    const int pim0 = pos0 & (HW - 1);

    for (int idx = tid; idx < 1152; idx += 256) {
        int k = idx >> 7, p = idx & 127;
        int gidx = (b*KK + k)*HW + pim0 + p;
        float py = g_py[gidx], px = g_px[gidx], mk = g_mk[gidx];
        float fy = floorf(py), fx = floorf(px);
        float wy = py - fy, wx = px - fx;
        int y0 = (int)fy, x0 = (int)fx;
        bool y0k = ((unsigned)y0 < HH), y1k = ((unsigned)(y0+1) < HH);
        bool x0k = ((unsigned)x0 < WW), x1k = ((unsigned)(x0+1) < WW);
        float w00 = (y0k && x0k) ? (1.f-wy)*(1.f-wx)*mk : 0.f;
        float w01 = (y0k && x1k) ? (1.f-wy)*wx*mk       : 0.f;
        float w10 = (y1k && x0k) ? wy*(1.f-wx)*mk       : 0.f;
        float w11 = (y1k && x1k) ? wy*wx*mk             : 0.f;
        int iy0 = min(max(y0, 0), HH-1),     ix0 = min(max(x0, 0), WW-1);
        int iy1 = min(max(y0 + 1, 0), HH-1), ix1 = min(max(x0 + 1, 0), WW-1);
        float* e = cE + idx*8;
        ((uint32_t*)e)[0] = f2h2(w00, w00);
        ((uint32_t*)e)[1] = f2h2(w01, w01);
        ((uint32_t*)e)[2] = f2h2(w10, w10);
        ((uint32_t*)e)[3] = f2h2(w11, w11);
        ((int*)e)[4] = (iy0*WW + ix0)*PL;
        ((int*)e)[5] = (iy0*WW + ix1)*PL;
        ((int*)e)[6] = (iy1*WW + ix0)*PL;
        ((int*)e)[7] = (iy1*WW + ix1)*PL;
    }
    __syncthreads();

    const __half* nhwcH = g_nhwcH + (size_t)b * HW * PL;
    uint32_t* Aw = smw + SMF_A;
    uint32_t* Bw = smw + SMF_B;

    float acc[2][8][4];
#pragma unroll
    for (int mt = 0; mt < 2; mt++)
#pragma unroll
        for (int nt = 0; nt < 8; nt++)
#pragma unroll
            for (int i = 0; i < 4; i++) acc[mt][nt][i] = 0.f;

    for (int dc = 0; dc < 9; dc++) {
        // fill A: full tap, 128 channels per position (one cE read per position)
#pragma unroll
        for (int it = 0; it < 8; it++) {
            int p  = wrp*16 + it*2 + sp2;
            int ci = dc*128 + p;
            const uint4 wb = *(const uint4*)(cE + ci*8);
            const int4  iv = *(const int4*)(cE + ci*8 + 4);
            __half2 H0 = *(__half2*)&wb.x;
            __half2 H1 = *(__half2*)&wb.y;
            __half2 H2 = *(__half2*)&wb.z;
            __half2 H3 = *(__half2*)&wb.w;
            const __half* base = nhwcH + cq2*8;
            uint4 r0 = *(const uint4*)(base + iv.x);
            uint4 r1 = *(const uint4*)(base + iv.y);
            uint4 r2 = *(const uint4*)(base + iv.z);
            uint4 r3 = *(const uint4*)(base + iv.w);
            uint32_t o4[4];
#pragma unroll
            for (int j = 0; j < 4; j++) {
                __half2 s = __hmul2(((__half2*)&r0)[j], H0);
                s = __hfma2(((__half2*)&r1)[j], H1, s);
                s = __hfma2(((__half2*)&r2)[j], H2, s);
                s = __hfma2(((__half2*)&r3)[j], H3, s);
                o4[j] = *(uint32_t*)&s;
            }
            *(uint4*)&Aw[p*LDA3 + cq2*4] = make_uint4(o4[0], o4[1], o4[2], o4[3]);
        }
        // fill B: 64 kpair-rows x 128 outs
#pragma unroll
        for (int u = 0; u < 8; u++) {
            int q = u*256 + tid, rr = q >> 5, col4 = (q & 31) * 4;
            *(uint4*)&Bw[rr*LDB2 + col4] =
                *(const uint4*)&g_wDcH[((size_t)dc*64 + rr)*PL + col4];
        }
        __syncthreads();
#pragma unroll
        for (int s = 0; s < 8; s++) {
            const int bs = s*8;
            uint32_t a[2][4];
#pragma unroll
            for (int mt = 0; mt < 2; mt++) {
                int rb = m0 + mt*16 + g;
                a[mt][0] = Aw[rb*LDA3 + bs + t3];
                a[mt][1] = Aw[(rb + 8)*LDA3 + bs + t3];
                a[mt][2] = Aw[rb*LDA3 + bs + t3 + 4];
                a[mt][3] = Aw[(rb + 8)*LDA3 + bs + t3 + 4];
            }
#pragma unroll
            for (int nt = 0; nt < 8; nt++) {
                uint32_t bb[2];
                bb[0] = Bw[(bs + t3)*LDB2 + n0 + nt*8 + g];
                bb[1] = Bw[(bs + t3 + 4)*LDB2 + n0 + nt*8 + g];
                mma_f16(acc[0][nt], a[0], bb);
                mma_f16(acc[1][nt], a[1], bb);
            }
        }
        __syncthreads();
    }

    uint32_t* Vw = smw + SMF_V;
#pragma unroll
    for (int nt = 0; nt < 8; nt++) {
        int c0 = n0 + nt*8 + 2*t3;
        float b0 = __ldg(b_dc + c0),     ss0 = __ldg(s2 + c0),     tt0 = __ldg(t2 + c0);
        float b1 = __ldg(b_dc + c0 + 1), ss1 = __ldg(s2 + c0 + 1), tt1 = __ldg(t2 + c0 + 1);
#pragma unroll
        for (int mt = 0; mt < 2; mt++) {
            int plo = m0 + mt*16 + g;
            float v0 = fmaxf((acc[mt][nt][0] + b0) * ss0 + tt0, 0.f);
            float v1 = fmaxf((acc[mt][nt][1] + b1) * ss1 + tt1, 0.f);
            float v2 = fmaxf((acc[mt][nt][2] + b0) * ss0 + tt0, 0.f);
            float v3 = fmaxf((acc[mt][nt][3] + b1) * ss1 + tt1, 0.f);
            Vw[plo*LDV2 + (c0 >> 1)]       = f2h2(v0, v1);
            Vw[(plo + 8)*LDV2 + (c0 >> 1)] = f2h2(v2, v3);
        }
    }
    __syncthreads();

    float acc3[2][8][4];
#pragma unroll
    for (int mt = 0; mt < 2; mt++)
#pragma unroll
        for (int nt = 0; nt < 8; nt++)
#pragma unroll
            for (int i = 0; i < 4; i++) acc3[mt][nt][i] = 0.f;

    uint32_t* B2w = smw + SMF_B2;
    for (int d2 = 0; d2 < 2; d2++) {
#pragma unroll
        for (int u = 0; u < 4; u++) {
            int q = u*256 + tid, rr = q >> 5, col4 = (q & 31) * 4;
            *(uint4*)&B2w[rr*LDB2 + col4] =
                *(const uint4*)&g_w3H[((size_t)d2*32 + rr)*PL + col4];
        }
        __syncthreads();
#pragma unroll
        for (int s = 0; s < 4; s++) {
            const int bs = s*8;
            const int kw = d2*32 + bs;
            uint32_t a[2][4];
#pragma unroll
            for (int mt = 0; mt < 2; mt++) {
                int rb = m0 + mt*16 + g;
                a[mt][0] = Vw[rb*LDV2 + kw + t3];
                a[mt][1] = Vw[(rb + 8)*LDV2 + kw + t3];
                a[mt][2] = Vw[rb*LDV2 + kw + t3 + 4];
                a[mt][3] = Vw[(rb + 8)*LDV2 + kw + t3 + 4];
            }
#pragma unroll
            for (int nt = 0; nt < 8; nt++) {
                uint32_t bb[2];
                bb[0] = B2w[(bs + t3)*LDB2 + n0 + nt*8 + g];
                bb[1] = B2w[(bs + t3 + 4)*LDB2 + n0 + nt*8 + g];
                mma_f16(acc3[0][nt], a[0], bb);
                mma_f16(acc3[1][nt], a[1], bb);
            }
        }
        __syncthreads();
    }

    float* Fs = smf + SMF_V;
#pragma unroll
    for (int nt = 0; nt < 8; nt++) {
        int c0 = n0 + nt*8 + 2*t3;
        float sa0 = __ldg(s3a + c0),     ta0 = __ldg(t3a + c0);
        float sb0 = __ldg(s3b + c0),     tb0 = __ldg(t3b + c0);
        float sa1 = __ldg(s3a + c0 + 1), ta1 = __ldg(t3a + c0 + 1);
        float sb1 = __ldg(s3b + c0 + 1), tb1 = __ldg(t3b + c0 + 1);
#pragma unroll
        for (int mt = 0; mt < 2; mt++) {
            int plo = m0 + mt*16 + g;
            Fs[c0*LDP + plo]           = fmaxf(acc3[mt][nt][0] * sa0 + ta0, 0.f) * sb0 + tb0;
            Fs[(c0 + 1)*LDP + plo]     = fmaxf(acc3[mt][nt][1] * sa1 + ta1, 0.f) * sb1 + tb1;
            Fs[c0*LDP + plo + 8]       = fmaxf(acc3[mt][nt][2] * sa0 + ta0, 0.f) * sb0 + tb0;
            Fs[(c0 + 1)*LDP + plo + 8] = fmaxf(acc3[mt][nt][3] * sa1 + ta1, 0.f) * sb1 + tb1;
        }
    }
    __syncthreads();

    {
        const int o2 = tid & 127;
        const int ph = tid >> 7;
        size_t base = ((size_t)(b*PL + o2))*HW + pim0 + ph*64;
        const float* frow = Fs + o2*LDP + ph*64;
#pragma unroll
        for (int i = 0; i < 16; i++) {
            float4 f = *(const float4*)&frow[i*4];
            float4 id = *(const float4*)&g_ident[base + i*4];
            *(float4*)&out[base + i*4] = make_float4(
                fmaxf(f.x + id.x, 0.f), fmaxf(f.y + id.y, 0.f),
                fmaxf(f.z + id.z, 0.f), fmaxf(f.w + id.w, 0.f));
        }
    }
}

// ---------------- host ----------------
extern "C" void kernel_launch(void* const* d_in, const int* in_sizes, int n_in,
                              void* d_out, int out_size) {
    const float* x    = (const float*)d_in[0];
    const float* w1   = (const float*)d_in[1];
    const float* s1a  = (const float*)d_in[2];
    const float* t1a  = (const float*)d_in[3];
    const float* s1b  = (const float*)d_in[4];
    const float* t1b  = (const float*)d_in[5];
    const float* w_off= (const float*)d_in[6];
    const float* b_off= (const float*)d_in[7];
    const float* w_dc = (const float*)d_in[8];
    const float* b_dc = (const float*)d_in[9];
    const float* s2   = (const float*)d_in[10];
    const float* t2   = (const float*)d_in[11];
    const float* w3   = (const float*)d_in[12];
    const float* s3a  = (const float*)d_in[13];
    const float* t3a  = (const float*)d_in[14];
    const float* s3b  = (const float*)d_in[15];
    const float* t3b  = (const float*)d_in[16];
    const float* w_ds = (const float*)d_in[17];
    const float* b_ds = (const float*)d_in[18];
    const float* sd   = (const float*)d_in[19];
    const float* td   = (const float*)d_in[20];
    float* out = (float*)d_out;

    k_prep<<<(CK*PL/2 + 255)/256, 256>>>(w_off, w_dc, w3, w1, w_ds);

    cudaFuncSetAttribute(k_cgemm, cudaFuncAttributeMaxDynamicSharedMemorySize, SMEM_TOT_C);
    dim3 g1(HW/128, NB);
    k_cgemm<<<g1, 256, SMEM_TOT_C>>>(x, s1a, t1a, s1b, t1b);

    cudaFuncSetAttribute(k_mix, cudaFuncAttributeMaxDynamicSharedMemorySize, SMEM_TOT_C);
    k_mix<<<2*NB*HH, 256, SMEM_TOT_C>>>(b_off, x, b_ds, sd, td);

    cudaFuncSetAttribute(k_dgemm, cudaFuncAttributeMaxDynamicSharedMemorySize, SMEM_TOT);
    k_dgemm<<<NB*HW/128, 256, SMEM_TOT>>>(b_dc, s2, t2, s3a, t3a, s3b, t3b, out);
}